// round 9
// baseline (speedup 1.0000x reference)
#include <cuda_runtime.h>
#include <cuda_fp16.h>
#include <cstdint>

// features: [32, 768, 32, 32] -> F[b, c, hw], hw = 1024
// query:    [32, 16, 32, 32]  -> Q[b, q, hw]
// W:        [64, 16, 768]     -> A[r, c], r = k*16+q  (1024 x 768)
//
// dist2[b,k] = sum_{q,hw} (A@F_b - Q)^2 ; codes = argmin_k ; sel = recompute.
// GEMM in pure fp16 mma.sync (dist2 err std ~0.14 << argmin gap ~150).
// sel + commit_loss recomputed EXACTLY in fp32, so output precision is fp32.

#define FN   (32 * 768 * 1024)
#define WN   (1024 * 768)

__device__ __half g_Fh[FN];
__device__ __half g_Wh[WN];
__device__ float g_dist2_part[32 * 512];   // [b][k(64)][hwtile(8)]
__device__ int   g_codes[32];
__device__ float g_loss_part[1024];

// ---------------- PTX helpers ----------------
__device__ __forceinline__ uint32_t smem_u32(const void* p) {
    uint32_t a;
    asm("{ .reg .u64 t; cvta.to.shared.u64 t, %1; cvt.u32.u64 %0, t; }" : "=r"(a) : "l"(p));
    return a;
}
__device__ __forceinline__ void cp16(uint32_t dst, const void* src) {
    asm volatile("cp.async.cg.shared.global [%0], [%1], 16;" :: "r"(dst), "l"(src));
}
#define CP_COMMIT() asm volatile("cp.async.commit_group;" ::: "memory")
#define CP_WAIT(n)  asm volatile("cp.async.wait_group %0;" :: "n"(n) : "memory")

__device__ __forceinline__ void ldsm_x4(uint32_t addr, uint32_t* r) {
    asm volatile("ldmatrix.sync.aligned.m8n8.x4.shared.b16 {%0,%1,%2,%3}, [%4];"
                 : "=r"(r[0]), "=r"(r[1]), "=r"(r[2]), "=r"(r[3]) : "r"(addr));
}
__device__ __forceinline__ void ldsm_x4_t(uint32_t addr, uint32_t* r) {
    asm volatile("ldmatrix.sync.aligned.m8n8.x4.trans.shared.b16 {%0,%1,%2,%3}, [%4];"
                 : "=r"(r[0]), "=r"(r[1]), "=r"(r[2]), "=r"(r[3]) : "r"(addr));
}
__device__ __forceinline__ void mma_f16(float* c, const uint32_t* a, const uint32_t* b) {
    asm volatile(
        "mma.sync.aligned.m16n8k16.row.col.f32.f16.f16.f32 "
        "{%0,%1,%2,%3},{%4,%5,%6,%7},{%8,%9},{%0,%1,%2,%3};"
        : "+f"(c[0]), "+f"(c[1]), "+f"(c[2]), "+f"(c[3])
        : "r"(a[0]), "r"(a[1]), "r"(a[2]), "r"(a[3]), "r"(b[0]), "r"(b[1]));
}

// ---------------- fp32 -> fp16 pre-conversion ----------------
__global__ void convF_kernel(const float* __restrict__ F) {
    const float4* src = (const float4*)F;
    __half2* h2 = reinterpret_cast<__half2*>(g_Fh);
    const int n4 = FN / 4;
    for (int i = blockIdx.x * blockDim.x + threadIdx.x; i < n4;
         i += gridDim.x * blockDim.x) {
        float4 v = src[i];
        h2[i * 2 + 0] = __floats2half2_rn(v.x, v.y);
        h2[i * 2 + 1] = __floats2half2_rn(v.z, v.w);
    }
}
__global__ void convW_kernel(const float* __restrict__ W) {
    const float4* src = (const float4*)W;
    __half2* h2 = reinterpret_cast<__half2*>(g_Wh);
    const int n4 = WN / 4;
    for (int i = blockIdx.x * blockDim.x + threadIdx.x; i < n4;
         i += gridDim.x * blockDim.x) {
        float4 v = src[i];
        h2[i * 2 + 0] = __floats2half2_rn(v.x, v.y);
        h2[i * 2 + 1] = __floats2half2_rn(v.z, v.w);
    }
}

// ---------------- dist GEMM: fp16 mma.sync ----------------
// CTA tile 256x128, 8 warps (warp tile 64x64), chunk K=32,
// 5-stage cp.async ring, load-issue ahead of wait+barrier.
// smem stage: A[256][80B] @0 (20480), B[32][272B] @20480 (8704). stage=29184.
#define ST_B    20480
#define STAGE   29184
#define NSTAGE  5
#define DSMEM   (NSTAGE * STAGE + 128)

__device__ __forceinline__ void load_stage(
    int t, int kb, uint32_t sbase, int rowBase, int colBase, size_t Foff)
{
    // A: 256 rows x 32 fp16 = 64B/row = 4 x 16B chunks -> 1024 cp16, 4/thread
    #pragma unroll
    for (int it = 0; it < 4; ++it) {
        int o = it * 256 + t;
        int row = o >> 2, seg = o & 3;
        const __half* s = g_Wh + (size_t)(rowBase + row) * 768 + kb + seg * 8;
        cp16(sbase + row * 80 + seg * 16, s);
    }
    // B: 32 rows x 128 fp16 = 256B/row = 16 x 16B chunks -> 512 cp16, 2/thread
    #pragma unroll
    for (int it = 0; it < 2; ++it) {
        int o = it * 256 + t;
        int row = o >> 4, seg = o & 15;
        const __half* s = g_Fh + Foff + (size_t)(kb + row) * 1024 + colBase + seg * 8;
        cp16(sbase + ST_B + row * 272 + seg * 16, s);
    }
}

__global__ __launch_bounds__(256, 1)
void dist_gemm_mma(const float* __restrict__ Q)
{
    extern __shared__ char smem[];
    const uint32_t sb = smem_u32(smem);
    float* sred = (float*)(smem + NSTAGE * STAGE);   // [16 k][2 colgrp]

    const int t    = threadIdx.x;
    const int wid  = t >> 5;        // 0..7
    const int lane = t & 31;
    const int wr   = wid & 3;       // warp row group (64 rows each, 4 groups)
    const int wc   = wid >> 2;      // warp col group (64 cols each, 2 groups)
    const int b       = blockIdx.z;
    const int rowBase = blockIdx.y * 256;
    const int colBase = blockIdx.x * 128;
    const size_t Foff = (size_t)b * 768 * 1024;

    uint32_t a_addr[4];
    #pragma unroll
    for (int rt = 0; rt < 4; ++rt) {
        int row = wr * 64 + rt * 16 + (lane & 15);
        a_addr[rt] = sb + row * 80 + ((lane >> 4) * 16);
    }
    uint32_t b_addr[4];
    #pragma unroll
    for (int p = 0; p < 4; ++p) {
        int n = wc * 64 + p * 16 + (lane >> 4) * 8;
        b_addr[p] = sb + ST_B + (lane & 15) * 272 + n * 2;
    }

    float acc[4][8][4];
    #pragma unroll
    for (int i = 0; i < 4; ++i)
        #pragma unroll
        for (int j = 0; j < 8; ++j)
            #pragma unroll
            for (int v = 0; v < 4; ++v) acc[i][j][v] = 0.0f;

    // prologue: chunks 0..2 into stages 0..2
    load_stage(t, 0, sb, rowBase, colBase, Foff);
    CP_COMMIT();
    load_stage(t, 32, sb + STAGE, rowBase, colBase, Foff);
    CP_COMMIT();
    load_stage(t, 64, sb + 2 * STAGE, rowBase, colBase, Foff);
    CP_COMMIT();

    for (int kt = 0; kt < 24; ++kt) {
        // issue chunk kt+3 into stage (kt+3)%5 BEFORE waiting.
        // That stage was consumed at iter kt-2, fenced by iter kt-1's barrier.
        if (kt + 3 < 24)
            load_stage(t, (kt + 3) * 32, sb + ((kt + 3) % NSTAGE) * STAGE,
                       rowBase, colBase, Foff);
        CP_COMMIT();          // always commit (keeps group arithmetic exact)
        CP_WAIT(3);           // chunk kt resident
        __syncthreads();      // all warps past chunk kt-1's compute

        const uint32_t soff = (kt % NSTAGE) * STAGE;
        #pragma unroll
        for (int ks = 0; ks < 2; ++ks) {
            uint32_t ah[4][4], bh[16];
            const uint32_t aoff = soff + ks * 32;
            const uint32_t boff = soff + ks * (16 * 272);
            #pragma unroll
            for (int rt = 0; rt < 4; ++rt)
                ldsm_x4(a_addr[rt] + aoff, ah[rt]);
            #pragma unroll
            for (int p = 0; p < 4; ++p)
                ldsm_x4_t(b_addr[p] + boff, &bh[p * 4]);
            #pragma unroll
            for (int rt = 0; rt < 4; ++rt)
                #pragma unroll
                for (int nt = 0; nt < 8; ++nt)
                    mma_f16(acc[rt][nt], ah[rt], &bh[nt * 2]);
        }
    }

    // ---- epilogue: (C - Q)^2, deterministic reduction per k-group ----
    // Each rt tile (16 rows) is one k group: k_local = wr*4 + rt (0..15).
    const int qr0 = lane >> 2;
    const int cb  = colBase + wc * 64;
    float2 qa[8], qb[8];
    #pragma unroll
    for (int nt = 0; nt < 8; ++nt) {
        const float* q0 = Q + (size_t)b * 16384 + (size_t)qr0 * 1024 + cb + nt * 8 + (lane & 3) * 2;
        qa[nt] = *(const float2*)q0;
        qb[nt] = *(const float2*)(q0 + 8 * 1024);
    }
    __syncthreads();   // stages idle; sred region safe
    #pragma unroll
    for (int rt = 0; rt < 4; ++rt) {
        float rs = 0.0f;
        #pragma unroll
        for (int nt = 0; nt < 8; ++nt) {
            float d0 = acc[rt][nt][0] - qa[nt].x;
            float d1 = acc[rt][nt][1] - qa[nt].y;
            float d2 = acc[rt][nt][2] - qb[nt].x;
            float d3 = acc[rt][nt][3] - qb[nt].y;
            rs += d0 * d0 + d1 * d1 + d2 * d2 + d3 * d3;
        }
        #pragma unroll
        for (int off = 16; off > 0; off >>= 1)
            rs += __shfl_xor_sync(0xffffffffu, rs, off);
        if (lane == 0) sred[(wr * 4 + rt) * 2 + wc] = rs;
    }
    __syncthreads();
    if (t < 16) {
        float s = sred[t * 2 + 0] + sred[t * 2 + 1];
        const int k = blockIdx.y * 16 + t;
        g_dist2_part[b * 512 + k * 8 + blockIdx.x] = s;
    }
}

// ---------------- argmin: 1 block, warp-per-batch ----------------
__global__ __launch_bounds__(1024)
void argmin_kernel(float* __restrict__ out)
{
    const int b    = threadIdx.x >> 5;   // 32 warps = 32 batches
    const int lane = threadIdx.x & 31;

    float v[2];
    #pragma unroll
    for (int j = 0; j < 2; ++j) {
        const int k = lane * 2 + j;
        const float4* p = (const float4*)(g_dist2_part + b * 512 + k * 8);
        float4 x = p[0], y = p[1];
        v[j] = (x.x + x.y) + (x.z + x.w) + (y.x + y.y) + (y.z + y.w);
    }
    float best = v[0] < v[1] ? v[0] : v[1];
    int   bi   = v[0] < v[1] ? lane * 2 : lane * 2 + 1;
    #pragma unroll
    for (int off = 16; off > 0; off >>= 1) {
        float ov = __shfl_xor_sync(0xffffffffu, best, off);
        int   oi = __shfl_xor_sync(0xffffffffu, bi,   off);
        if (ov < best || (ov == best && oi < bi)) { best = ov; bi = oi; }
    }
    if (lane == 0) {
        g_codes[b] = bi;
        out[524288 + b] = (float)bi;
    }
}

// ---------------- sel recompute (fp32 exact) + loss partials ----------------
// grid = (32 col-tiles, 32 batches), 256 threads = 32 cols x 8 c-partitions.
__global__ __launch_bounds__(256)
void sel_kernel(const float* __restrict__ F,
                const float* __restrict__ Q,
                const float* __restrict__ W,
                float* __restrict__ out)
{
    const int b    = blockIdx.y;
    const int col  = blockIdx.x * 32 + (threadIdx.x & 31);
    const int part = threadIdx.x >> 5;       // 0..7, each owns 96 c's
    const int code = g_codes[b];

    const float* wp = W + (size_t)code * 16 * 768;
    const float* f  = F + (size_t)b * 768 * 1024 + col;

    float acc[16];
    #pragma unroll
    for (int q = 0; q < 16; ++q) acc[q] = 0.0f;

    const int c0 = part * 96;
    for (int c = c0; c < c0 + 96; c += 8) {
        float fv[8];
        #pragma unroll
        for (int u = 0; u < 8; ++u)
            fv[u] = __ldg(&f[(size_t)(c + u) * 1024]);
        #pragma unroll
        for (int q = 0; q < 16; ++q) {
            const float4 w0 = *(const float4*)&wp[q * 768 + c];
            const float4 w1 = *(const float4*)&wp[q * 768 + c + 4];
            acc[q] += w0.x * fv[0] + w0.y * fv[1] + w0.z * fv[2] + w0.w * fv[3];
            acc[q] += w1.x * fv[4] + w1.y * fv[5] + w1.z * fv[6] + w1.w * fv[7];
        }
    }

    __shared__ float red[8][16][32];
    const int lane = threadIdx.x & 31;
    #pragma unroll
    for (int q = 0; q < 16; ++q) red[part][q][lane] = acc[q];
    __syncthreads();

    if (part == 0) {
        float* op = out + (size_t)b * 16 * 1024 + col;
        const float* qp = Q + (size_t)b * 16 * 1024 + col;
        float lsum = 0.0f;
        #pragma unroll
        for (int q = 0; q < 16; ++q) {
            float s = red[0][q][lane] + red[1][q][lane]
                    + red[2][q][lane] + red[3][q][lane]
                    + red[4][q][lane] + red[5][q][lane]
                    + red[6][q][lane] + red[7][q][lane];
            op[(size_t)q * 1024] = s;
            float d = s - qp[(size_t)q * 1024];
            lsum += d * d;
        }
        #pragma unroll
        for (int off = 16; off > 0; off >>= 1)
            lsum += __shfl_xor_sync(0xffffffffu, lsum, off);
        if (lane == 0)
            g_loss_part[b * 32 + blockIdx.x] = lsum;
    }
}

__global__ void loss_final(float* __restrict__ out)
{
    __shared__ float s[1024];
    const int t = threadIdx.x;
    s[t] = g_loss_part[t];
    __syncthreads();
    for (int o = 512; o > 0; o >>= 1) {
        if (t < o) s[t] += s[t + o];
        __syncthreads();
    }
    if (t == 0) out[524320] = s[0] / 524288.0f;
}

extern "C" void kernel_launch(void* const* d_in, const int* in_sizes, int n_in,
                              void* d_out, int out_size)
{
    const float* F = (const float*)d_in[0];
    const float* Q = (const float*)d_in[1];
    const float* W = (const float*)d_in[2];
    float* out = (float*)d_out;

    cudaFuncSetAttribute(dist_gemm_mma,
                         cudaFuncAttributeMaxDynamicSharedMemorySize, DSMEM);

    convF_kernel<<<2048, 256>>>(F);
    convW_kernel<<<768, 256>>>(W);
    dist_gemm_mma<<<dim3(8, 4, 32), 256, DSMEM>>>(Q);
    argmin_kernel<<<1, 1024>>>(out);
    sel_kernel<<<dim3(32, 32), 256>>>(F, Q, W, out);
    loss_final<<<1, 1024>>>(out);
}

// round 11
// speedup vs baseline: 1.1492x; 1.1492x over previous
#include <cuda_runtime.h>
#include <cuda_fp16.h>
#include <cstdint>

// features: [32, 768, 32, 32] -> F[b, c, hw], hw = 1024
// query:    [32, 16, 32, 32]  -> Q[b, q, hw]
// W:        [64, 16, 768]     -> A[r, c], r = k*16+q  (1024 x 768)
//
// dist2[b,k] = sum_{q,hw} (A@F_b - Q)^2 ; codes = argmin_k ; sel = recompute.
// GEMM in pure fp16 mma.sync (dist2 err std ~0.14 << argmin gap ~150).
// sel + commit_loss recomputed EXACTLY in fp32, so output precision is fp32.

#define FN   (32 * 768 * 1024)
#define WN   (1024 * 768)

__device__ __half g_Fh[FN];
__device__ __half g_Wh[WN];
__device__ float g_dist2_part[32 * 512];   // [b][k(64)][hwtile(8)]
__device__ int   g_codes[32];
__device__ float g_loss_part[1024];

// ---------------- PTX helpers ----------------
__device__ __forceinline__ uint32_t smem_u32(const void* p) {
    uint32_t a;
    asm("{ .reg .u64 t; cvta.to.shared.u64 t, %1; cvt.u32.u64 %0, t; }" : "=r"(a) : "l"(p));
    return a;
}
__device__ __forceinline__ void cp16(uint32_t dst, const void* src) {
    asm volatile("cp.async.cg.shared.global [%0], [%1], 16;" :: "r"(dst), "l"(src));
}
#define CP_COMMIT() asm volatile("cp.async.commit_group;" ::: "memory")
#define CP_WAIT(n)  asm volatile("cp.async.wait_group %0;" :: "n"(n) : "memory")

__device__ __forceinline__ void ldsm_x4(uint32_t addr, uint32_t* r) {
    asm volatile("ldmatrix.sync.aligned.m8n8.x4.shared.b16 {%0,%1,%2,%3}, [%4];"
                 : "=r"(r[0]), "=r"(r[1]), "=r"(r[2]), "=r"(r[3]) : "r"(addr));
}
__device__ __forceinline__ void ldsm_x4_t(uint32_t addr, uint32_t* r) {
    asm volatile("ldmatrix.sync.aligned.m8n8.x4.trans.shared.b16 {%0,%1,%2,%3}, [%4];"
                 : "=r"(r[0]), "=r"(r[1]), "=r"(r[2]), "=r"(r[3]) : "r"(addr));
}
__device__ __forceinline__ void mma_f16(float* c, const uint32_t* a, const uint32_t* b) {
    asm volatile(
        "mma.sync.aligned.m16n8k16.row.col.f32.f16.f16.f32 "
        "{%0,%1,%2,%3},{%4,%5,%6,%7},{%8,%9},{%0,%1,%2,%3};"
        : "+f"(c[0]), "+f"(c[1]), "+f"(c[2]), "+f"(c[3])
        : "r"(a[0]), "r"(a[1]), "r"(a[2]), "r"(a[3]), "r"(b[0]), "r"(b[1]));
}

// ---------------- fp32 -> fp16 pre-conversion (F and W in one launch) ----------------
#define CONV_F_BLOCKS 2048
#define CONV_W_BLOCKS 192
__global__ void conv_kernel(const float* __restrict__ F, const float* __restrict__ W) {
    if (blockIdx.x < CONV_F_BLOCKS) {
        const float4* src = (const float4*)F;
        __half2* h2 = reinterpret_cast<__half2*>(g_Fh);
        const int n4 = FN / 4;
        for (int i = blockIdx.x * blockDim.x + threadIdx.x; i < n4;
             i += CONV_F_BLOCKS * blockDim.x) {
            float4 v = src[i];
            h2[i * 2 + 0] = __floats2half2_rn(v.x, v.y);
            h2[i * 2 + 1] = __floats2half2_rn(v.z, v.w);
        }
    } else {
        const float4* src = (const float4*)W;
        __half2* h2 = reinterpret_cast<__half2*>(g_Wh);
        const int n4 = WN / 4;
        for (int i = (blockIdx.x - CONV_F_BLOCKS) * blockDim.x + threadIdx.x; i < n4;
             i += CONV_W_BLOCKS * blockDim.x) {
            float4 v = src[i];
            h2[i * 2 + 0] = __floats2half2_rn(v.x, v.y);
            h2[i * 2 + 1] = __floats2half2_rn(v.z, v.w);
        }
    }
}

// ---------------- dist GEMM: fp16 mma.sync (R8 structure, proven) ----------------
// CTA tile 128x128, 4 warps (warp tile 64x64), chunk K=32, 2 CTAs/SM.
// 5-stage cp.async ring; per iteration: load(kt+3) -> commit -> wait(3) ->
// __syncthreads -> compute(kt). The wait-then-barrier order is what makes
// other warps' async copies visible before any warp consumes the tile.
#define ST_B    10240
#define STAGE   18944
#define NSTAGE  5
#define DSMEM   (NSTAGE * STAGE + 64)

__device__ __forceinline__ void load_stage(
    int t, int kb, uint32_t sbase, int rowBase, int colBase, size_t Foff)
{
    // A: 128 rows x 32 fp16 = 64B/row = 4 x 16B chunks -> 512 cp16, 4/thread
    #pragma unroll
    for (int it = 0; it < 4; ++it) {
        int o = it * 128 + t;
        int row = o >> 2, seg = o & 3;
        const __half* s = g_Wh + (size_t)(rowBase + row) * 768 + kb + seg * 8;
        cp16(sbase + row * 80 + seg * 16, s);
    }
    // B: 32 rows x 128 fp16 = 256B/row = 16 x 16B chunks -> 512 cp16, 4/thread
    #pragma unroll
    for (int it = 0; it < 4; ++it) {
        int o = it * 128 + t;
        int row = o >> 4, seg = o & 15;
        const __half* s = g_Fh + Foff + (size_t)(kb + row) * 1024 + colBase + seg * 8;
        cp16(sbase + ST_B + row * 272 + seg * 16, s);
    }
}

__global__ __launch_bounds__(128, 2)
void dist_gemm_mma(const float* __restrict__ Q)
{
    extern __shared__ char smem[];
    const uint32_t sb = smem_u32(smem);
    float* sred = (float*)(smem + NSTAGE * STAGE);   // [8 k][2 colgrp]

    const int t    = threadIdx.x;
    const int wid  = t >> 5;        // 0..3
    const int lane = t & 31;
    const int wr   = wid & 1;       // warp row group (64 rows)
    const int wc   = wid >> 1;      // warp col group (64 cols)
    const int b       = blockIdx.z;
    const int rowBase = blockIdx.y * 128;
    const int colBase = blockIdx.x * 128;
    const size_t Foff = (size_t)b * 768 * 1024;

    uint32_t a_addr[4];
    #pragma unroll
    for (int rt = 0; rt < 4; ++rt) {
        int row = wr * 64 + rt * 16 + (lane & 15);
        a_addr[rt] = sb + row * 80 + ((lane >> 4) * 16);
    }
    uint32_t b_addr[4];
    #pragma unroll
    for (int p = 0; p < 4; ++p) {
        int n = wc * 64 + p * 16 + (lane >> 4) * 8;
        b_addr[p] = sb + ST_B + (lane & 15) * 272 + n * 2;
    }

    float acc[4][8][4];
    #pragma unroll
    for (int i = 0; i < 4; ++i)
        #pragma unroll
        for (int j = 0; j < 8; ++j)
            #pragma unroll
            for (int v = 0; v < 4; ++v) acc[i][j][v] = 0.0f;

    // prologue: chunks 0..2 into stages 0..2
    load_stage(t, 0, sb, rowBase, colBase, Foff);
    CP_COMMIT();
    load_stage(t, 32, sb + STAGE, rowBase, colBase, Foff);
    CP_COMMIT();
    load_stage(t, 64, sb + 2 * STAGE, rowBase, colBase, Foff);
    CP_COMMIT();

    for (int kt = 0; kt < 24; ++kt) {
        // issue chunk kt+3 into stage (kt+3)%5 (consumed at iter kt-2,
        // separated from this write by iter kt-1's barrier).
        if (kt + 3 < 24)
            load_stage(t, (kt + 3) * 32, sb + ((kt + 3) % NSTAGE) * STAGE,
                       rowBase, colBase, Foff);
        CP_COMMIT();          // always commit (keeps group arithmetic exact)
        CP_WAIT(3);           // this warp's chunk-kt copies resident
        __syncthreads();      // -> ALL warps' chunk-kt copies visible

        const uint32_t soff = (kt % NSTAGE) * STAGE;
        #pragma unroll
        for (int ks = 0; ks < 2; ++ks) {
            uint32_t ah[4][4], bh[16];
            const uint32_t aoff = soff + ks * 32;
            const uint32_t boff = soff + ks * (16 * 272);
            #pragma unroll
            for (int rt = 0; rt < 4; ++rt)
                ldsm_x4(a_addr[rt] + aoff, ah[rt]);
            #pragma unroll
            for (int p = 0; p < 4; ++p)
                ldsm_x4_t(b_addr[p] + boff, &bh[p * 4]);
            #pragma unroll
            for (int rt = 0; rt < 4; ++rt)
                #pragma unroll
                for (int nt = 0; nt < 8; ++nt)
                    mma_f16(acc[rt][nt], ah[rt], &bh[nt * 2]);
        }
    }

    // ---- epilogue: (C - Q)^2, deterministic reduction per k-group ----
    // Each rt tile (16 rows) is exactly one k group: k_local = wr*4 + rt.
    const int qr0 = lane >> 2;
    const int cb  = colBase + wc * 64;
    float2 qa[8], qb[8];
    #pragma unroll
    for (int nt = 0; nt < 8; ++nt) {
        const float* q0 = Q + (size_t)b * 16384 + (size_t)qr0 * 1024 + cb + nt * 8 + (lane & 3) * 2;
        qa[nt] = *(const float2*)q0;
        qb[nt] = *(const float2*)(q0 + 8 * 1024);
    }
    __syncthreads();   // stages idle; sred region safe
    #pragma unroll
    for (int rt = 0; rt < 4; ++rt) {
        float rs = 0.0f;
        #pragma unroll
        for (int nt = 0; nt < 8; ++nt) {
            float d0 = acc[rt][nt][0] - qa[nt].x;
            float d1 = acc[rt][nt][1] - qa[nt].y;
            float d2 = acc[rt][nt][2] - qb[nt].x;
            float d3 = acc[rt][nt][3] - qb[nt].y;
            rs += d0 * d0 + d1 * d1 + d2 * d2 + d3 * d3;
        }
        #pragma unroll
        for (int off = 16; off > 0; off >>= 1)
            rs += __shfl_xor_sync(0xffffffffu, rs, off);
        if (lane == 0) sred[(wr * 4 + rt) * 2 + wc] = rs;
    }
    __syncthreads();
    if (t < 8) {
        float s = sred[t * 2 + 0] + sred[t * 2 + 1];
        const int k = blockIdx.y * 8 + t;
        g_dist2_part[b * 512 + k * 8 + blockIdx.x] = s;   // [b][k][hwtile]
    }
}

// ---------------- argmin: 1 block, warp-per-batch, contiguous float4 ----------------
__global__ __launch_bounds__(1024)
void argmin_kernel(float* __restrict__ out)
{
    const int b    = threadIdx.x >> 5;   // 32 warps = 32 batches
    const int lane = threadIdx.x & 31;

    float v[2];
    #pragma unroll
    for (int j = 0; j < 2; ++j) {
        const int k = lane * 2 + j;
        const float4* p = (const float4*)(g_dist2_part + b * 512 + k * 8);
        float4 x = p[0], y = p[1];
        v[j] = (x.x + x.y) + (x.z + x.w) + (y.x + y.y) + (y.z + y.w);
    }
    float best = v[0] < v[1] ? v[0] : v[1];
    int   bi   = v[0] < v[1] ? lane * 2 : lane * 2 + 1;
    #pragma unroll
    for (int off = 16; off > 0; off >>= 1) {
        float ov = __shfl_xor_sync(0xffffffffu, best, off);
        int   oi = __shfl_xor_sync(0xffffffffu, bi,   off);
        if (ov < best || (ov == best && oi < bi)) { best = ov; bi = oi; }
    }
    if (lane == 0) {
        g_codes[b] = bi;
        out[524288 + b] = (float)bi;
    }
}

// ---------------- sel recompute (fp32 exact) + loss partials ----------------
// grid = (32 col-tiles, 32 batches), 256 threads = 32 cols x 8 c-partitions.
__global__ __launch_bounds__(256)
void sel_kernel(const float* __restrict__ F,
                const float* __restrict__ Q,
                const float* __restrict__ W,
                float* __restrict__ out)
{
    const int b    = blockIdx.y;
    const int col  = blockIdx.x * 32 + (threadIdx.x & 31);
    const int part = threadIdx.x >> 5;       // 0..7, each owns 96 c's
    const int code = g_codes[b];

    const float* wp = W + (size_t)code * 16 * 768;
    const float* f  = F + (size_t)b * 768 * 1024 + col;

    float acc[16];
    #pragma unroll
    for (int q = 0; q < 16; ++q) acc[q] = 0.0f;

    const int c0 = part * 96;
    for (int c = c0; c < c0 + 96; c += 8) {
        float fv[8];
        #pragma unroll
        for (int u = 0; u < 8; ++u)
            fv[u] = __ldg(&f[(size_t)(c + u) * 1024]);
        #pragma unroll
        for (int q = 0; q < 16; ++q) {
            const float4 w0 = *(const float4*)&wp[q * 768 + c];
            const float4 w1 = *(const float4*)&wp[q * 768 + c + 4];
            acc[q] += w0.x * fv[0] + w0.y * fv[1] + w0.z * fv[2] + w0.w * fv[3];
            acc[q] += w1.x * fv[4] + w1.y * fv[5] + w1.z * fv[6] + w1.w * fv[7];
        }
    }

    __shared__ float red[8][16][32];
    const int lane = threadIdx.x & 31;
    #pragma unroll
    for (int q = 0; q < 16; ++q) red[part][q][lane] = acc[q];
    __syncthreads();

    if (part == 0) {
        float* op = out + (size_t)b * 16 * 1024 + col;
        const float* qp = Q + (size_t)b * 16 * 1024 + col;
        float lsum = 0.0f;
        #pragma unroll
        for (int q = 0; q < 16; ++q) {
            float s = red[0][q][lane] + red[1][q][lane]
                    + red[2][q][lane] + red[3][q][lane]
                    + red[4][q][lane] + red[5][q][lane]
                    + red[6][q][lane] + red[7][q][lane];
            op[(size_t)q * 1024] = s;
            float d = s - qp[(size_t)q * 1024];
            lsum += d * d;
        }
        #pragma unroll
        for (int off = 16; off > 0; off >>= 1)
            lsum += __shfl_xor_sync(0xffffffffu, lsum, off);
        if (lane == 0)
            g_loss_part[b * 32 + blockIdx.x] = lsum;
    }
}

__global__ void loss_final(float* __restrict__ out)
{
    __shared__ float s[1024];
    const int t = threadIdx.x;
    s[t] = g_loss_part[t];
    __syncthreads();
    for (int o = 512; o > 0; o >>= 1) {
        if (t < o) s[t] += s[t + o];
        __syncthreads();
    }
    if (t == 0) out[524320] = s[0] / 524288.0f;
}

extern "C" void kernel_launch(void* const* d_in, const int* in_sizes, int n_in,
                              void* d_out, int out_size)
{
    const float* F = (const float*)d_in[0];
    const float* Q = (const float*)d_in[1];
    const float* W = (const float*)d_in[2];
    float* out = (float*)d_out;

    cudaFuncSetAttribute(dist_gemm_mma,
                         cudaFuncAttributeMaxDynamicSharedMemorySize, DSMEM);

    conv_kernel<<<CONV_F_BLOCKS + CONV_W_BLOCKS, 256>>>(F, W);
    dist_gemm_mma<<<dim3(8, 8, 32), 128, DSMEM>>>(Q);
    argmin_kernel<<<1, 1024>>>(out);
    sel_kernel<<<dim3(32, 32), 256>>>(F, Q, W, out);
    loss_final<<<1, 1024>>>(out);
}

// round 12
// speedup vs baseline: 1.1804x; 1.0272x over previous
#include <cuda_runtime.h>
#include <cuda_fp16.h>
#include <cstdint>

// features: [32, 768, 32, 32] -> F[b, c, hw], hw = 1024
// query:    [32, 16, 32, 32]  -> Q[b, q, hw]
// W:        [64, 16, 768]     -> A[r, c], r = k*16+q  (1024 x 768)
//
// dist2[b,k] = sum_{q,hw} (A@F_b - Q)^2 ; codes = argmin_k ; sel = recompute.
// GEMM in pure fp16 mma.sync (dist2 err std ~0.14 << argmin gap ~150).
// sel + commit_loss recomputed EXACTLY in fp32 (FFMA2 = packed exact fp32).

#define FN   (32 * 768 * 1024)
#define WN   (1024 * 768)

__device__ __half g_Fh[FN];
__device__ __half g_Wh[WN];
__device__ float g_dist2_part[32 * 512];   // [b][k(64)][hwtile(8)]
__device__ int   g_codes[32];
__device__ float g_loss_part[1024];

// ---------------- PTX helpers ----------------
__device__ __forceinline__ uint32_t smem_u32(const void* p) {
    uint32_t a;
    asm("{ .reg .u64 t; cvta.to.shared.u64 t, %1; cvt.u32.u64 %0, t; }" : "=r"(a) : "l"(p));
    return a;
}
__device__ __forceinline__ void cp16(uint32_t dst, const void* src) {
    asm volatile("cp.async.cg.shared.global [%0], [%1], 16;" :: "r"(dst), "l"(src));
}
#define CP_COMMIT() asm volatile("cp.async.commit_group;" ::: "memory")
#define CP_WAIT(n)  asm volatile("cp.async.wait_group %0;" :: "n"(n) : "memory")

__device__ __forceinline__ void ldsm_x4(uint32_t addr, uint32_t* r) {
    asm volatile("ldmatrix.sync.aligned.m8n8.x4.shared.b16 {%0,%1,%2,%3}, [%4];"
                 : "=r"(r[0]), "=r"(r[1]), "=r"(r[2]), "=r"(r[3]) : "r"(addr));
}
__device__ __forceinline__ void ldsm_x4_t(uint32_t addr, uint32_t* r) {
    asm volatile("ldmatrix.sync.aligned.m8n8.x4.trans.shared.b16 {%0,%1,%2,%3}, [%4];"
                 : "=r"(r[0]), "=r"(r[1]), "=r"(r[2]), "=r"(r[3]) : "r"(addr));
}
__device__ __forceinline__ void mma_f16(float* c, const uint32_t* a, const uint32_t* b) {
    asm volatile(
        "mma.sync.aligned.m16n8k16.row.col.f32.f16.f16.f32 "
        "{%0,%1,%2,%3},{%4,%5,%6,%7},{%8,%9},{%0,%1,%2,%3};"
        : "+f"(c[0]), "+f"(c[1]), "+f"(c[2]), "+f"(c[3])
        : "r"(a[0]), "r"(a[1]), "r"(a[2]), "r"(a[3]), "r"(b[0]), "r"(b[1]));
}

// packed f32x2 (exact: identical rounding to two scalar fmaf)
__device__ __forceinline__ unsigned long long bcast2(float x) {
    unsigned long long r;
    asm("mov.b64 %0, {%1, %1};" : "=l"(r) : "f"(x));
    return r;
}
__device__ __forceinline__ void ffma2(unsigned long long& d,
                                      unsigned long long a,
                                      unsigned long long b) {
    asm("fma.rn.f32x2 %0, %1, %2, %0;" : "+l"(d) : "l"(a), "l"(b));
}
__device__ __forceinline__ float lo32(unsigned long long v) {
    return __uint_as_float((unsigned)(v & 0xffffffffull));
}
__device__ __forceinline__ float hi32(unsigned long long v) {
    return __uint_as_float((unsigned)(v >> 32));
}

// ---------------- fp32 -> fp16 pre-conversion (F and W in one launch) ----------------
#define CONV_F_BLOCKS 2048
#define CONV_W_BLOCKS 192
__global__ void conv_kernel(const float* __restrict__ F, const float* __restrict__ W) {
    if (blockIdx.x < CONV_F_BLOCKS) {
        const float4* src = (const float4*)F;
        __half2* h2 = reinterpret_cast<__half2*>(g_Fh);
        const int n4 = FN / 4;
        for (int i = blockIdx.x * blockDim.x + threadIdx.x; i < n4;
             i += CONV_F_BLOCKS * blockDim.x) {
            float4 v = src[i];
            h2[i * 2 + 0] = __floats2half2_rn(v.x, v.y);
            h2[i * 2 + 1] = __floats2half2_rn(v.z, v.w);
        }
    } else {
        const float4* src = (const float4*)W;
        __half2* h2 = reinterpret_cast<__half2*>(g_Wh);
        const int n4 = WN / 4;
        for (int i = (blockIdx.x - CONV_F_BLOCKS) * blockDim.x + threadIdx.x; i < n4;
             i += CONV_W_BLOCKS * blockDim.x) {
            float4 v = src[i];
            h2[i * 2 + 0] = __floats2half2_rn(v.x, v.y);
            h2[i * 2 + 1] = __floats2half2_rn(v.z, v.w);
        }
    }
}

// ---------------- dist GEMM: fp16 mma.sync (R8 structure, proven) ----------------
#define ST_B    10240
#define STAGE   18944
#define NSTAGE  5
#define DSMEM   (NSTAGE * STAGE + 64)

__device__ __forceinline__ void load_stage(
    int t, int kb, uint32_t sbase, int rowBase, int colBase, size_t Foff)
{
    #pragma unroll
    for (int it = 0; it < 4; ++it) {
        int o = it * 128 + t;
        int row = o >> 2, seg = o & 3;
        const __half* s = g_Wh + (size_t)(rowBase + row) * 768 + kb + seg * 8;
        cp16(sbase + row * 80 + seg * 16, s);
    }
    #pragma unroll
    for (int it = 0; it < 4; ++it) {
        int o = it * 128 + t;
        int row = o >> 4, seg = o & 15;
        const __half* s = g_Fh + Foff + (size_t)(kb + row) * 1024 + colBase + seg * 8;
        cp16(sbase + ST_B + row * 272 + seg * 16, s);
    }
}

__global__ __launch_bounds__(128, 2)
void dist_gemm_mma(const float* __restrict__ Q)
{
    extern __shared__ char smem[];
    const uint32_t sb = smem_u32(smem);
    float* sred = (float*)(smem + NSTAGE * STAGE);   // [8 k][2 colgrp]

    const int t    = threadIdx.x;
    const int wid  = t >> 5;
    const int lane = t & 31;
    const int wr   = wid & 1;
    const int wc   = wid >> 1;
    const int b       = blockIdx.z;
    const int rowBase = blockIdx.y * 128;
    const int colBase = blockIdx.x * 128;
    const size_t Foff = (size_t)b * 768 * 1024;

    uint32_t a_addr[4];
    #pragma unroll
    for (int rt = 0; rt < 4; ++rt) {
        int row = wr * 64 + rt * 16 + (lane & 15);
        a_addr[rt] = sb + row * 80 + ((lane >> 4) * 16);
    }
    uint32_t b_addr[4];
    #pragma unroll
    for (int p = 0; p < 4; ++p) {
        int n = wc * 64 + p * 16 + (lane >> 4) * 8;
        b_addr[p] = sb + ST_B + (lane & 15) * 272 + n * 2;
    }

    float acc[4][8][4];
    #pragma unroll
    for (int i = 0; i < 4; ++i)
        #pragma unroll
        for (int j = 0; j < 8; ++j)
            #pragma unroll
            for (int v = 0; v < 4; ++v) acc[i][j][v] = 0.0f;

    load_stage(t, 0, sb, rowBase, colBase, Foff);
    CP_COMMIT();
    load_stage(t, 32, sb + STAGE, rowBase, colBase, Foff);
    CP_COMMIT();
    load_stage(t, 64, sb + 2 * STAGE, rowBase, colBase, Foff);
    CP_COMMIT();

    for (int kt = 0; kt < 24; ++kt) {
        if (kt + 3 < 24)
            load_stage(t, (kt + 3) * 32, sb + ((kt + 3) % NSTAGE) * STAGE,
                       rowBase, colBase, Foff);
        CP_COMMIT();
        CP_WAIT(3);           // this warp's chunk-kt copies resident
        __syncthreads();      // -> ALL warps' chunk-kt copies visible

        const uint32_t soff = (kt % NSTAGE) * STAGE;
        #pragma unroll
        for (int ks = 0; ks < 2; ++ks) {
            uint32_t ah[4][4], bh[16];
            const uint32_t aoff = soff + ks * 32;
            const uint32_t boff = soff + ks * (16 * 272);
            #pragma unroll
            for (int rt = 0; rt < 4; ++rt)
                ldsm_x4(a_addr[rt] + aoff, ah[rt]);
            #pragma unroll
            for (int p = 0; p < 4; ++p)
                ldsm_x4_t(b_addr[p] + boff, &bh[p * 4]);
            #pragma unroll
            for (int rt = 0; rt < 4; ++rt)
                #pragma unroll
                for (int nt = 0; nt < 8; ++nt)
                    mma_f16(acc[rt][nt], ah[rt], &bh[nt * 2]);
        }
    }

    // ---- epilogue: (C - Q)^2, deterministic reduction per k-group ----
    const int qr0 = lane >> 2;
    const int cb  = colBase + wc * 64;
    float2 qa[8], qb[8];
    #pragma unroll
    for (int nt = 0; nt < 8; ++nt) {
        const float* q0 = Q + (size_t)b * 16384 + (size_t)qr0 * 1024 + cb + nt * 8 + (lane & 3) * 2;
        qa[nt] = *(const float2*)q0;
        qb[nt] = *(const float2*)(q0 + 8 * 1024);
    }
    __syncthreads();
    #pragma unroll
    for (int rt = 0; rt < 4; ++rt) {
        float rs = 0.0f;
        #pragma unroll
        for (int nt = 0; nt < 8; ++nt) {
            float d0 = acc[rt][nt][0] - qa[nt].x;
            float d1 = acc[rt][nt][1] - qa[nt].y;
            float d2 = acc[rt][nt][2] - qb[nt].x;
            float d3 = acc[rt][nt][3] - qb[nt].y;
            rs += d0 * d0 + d1 * d1 + d2 * d2 + d3 * d3;
        }
        #pragma unroll
        for (int off = 16; off > 0; off >>= 1)
            rs += __shfl_xor_sync(0xffffffffu, rs, off);
        if (lane == 0) sred[(wr * 4 + rt) * 2 + wc] = rs;
    }
    __syncthreads();
    if (t < 8) {
        float s = sred[t * 2 + 0] + sred[t * 2 + 1];
        const int k = blockIdx.y * 8 + t;
        g_dist2_part[b * 512 + k * 8 + blockIdx.x] = s;
    }
}

// ---------------- argmin: 1 block, warp-per-batch ----------------
__global__ __launch_bounds__(1024)
void argmin_kernel(float* __restrict__ out)
{
    const int b    = threadIdx.x >> 5;
    const int lane = threadIdx.x & 31;

    float v[2];
    #pragma unroll
    for (int j = 0; j < 2; ++j) {
        const int k = lane * 2 + j;
        const float4* p = (const float4*)(g_dist2_part + b * 512 + k * 8);
        float4 x = p[0], y = p[1];
        v[j] = (x.x + x.y) + (x.z + x.w) + (y.x + y.y) + (y.z + y.w);
    }
    float best = v[0] < v[1] ? v[0] : v[1];
    int   bi   = v[0] < v[1] ? lane * 2 : lane * 2 + 1;
    #pragma unroll
    for (int off = 16; off > 0; off >>= 1) {
        float ov = __shfl_xor_sync(0xffffffffu, best, off);
        int   oi = __shfl_xor_sync(0xffffffffu, bi,   off);
        if (ov < best || (ov == best && oi < bi)) { best = ov; bi = oi; }
    }
    if (lane == 0) {
        g_codes[b] = bi;
        out[524288 + b] = (float)bi;
    }
}

// ---------------- sel recompute (fp32 exact via FFMA2) + loss partials ------
// grid = (32 col-tiles, 32 batches), 256 threads = 32 cols x 8 c-partitions.
// W[code] staged to smem in ws[c*16+q] layout: one lds.128 = 4 consecutive q
// = 2 packed f32x2 multiplicands. No W LDGs in the inner loop.
#define SEL_WS    (16 * 768 * 4)              // 49152 B
#define SEL_SMEM  (SEL_WS + 8 * 16 * 32 * 4)  // + red = 65536 B

__global__ __launch_bounds__(256)
void sel_kernel(const float* __restrict__ F,
                const float* __restrict__ Q,
                const float* __restrict__ W,
                float* __restrict__ out)
{
    extern __shared__ char ssel[];
    float* ws = (float*)ssel;                        // [768][16]
    float (*red)[16][32] = (float (*)[16][32])(ssel + SEL_WS);

    const int b    = blockIdx.y;
    const int col  = blockIdx.x * 32 + (threadIdx.x & 31);
    const int part = threadIdx.x >> 5;       // 0..7, each owns 96 c's
    const int lane = threadIdx.x & 31;
    const int code = g_codes[b];

    // stage W[code] (16 x 768, q-major in gmem) into ws[c*16+q]
    const float* wp = W + (size_t)code * 16 * 768;
    for (int i = threadIdx.x; i < 16 * 768; i += 256) {
        int q = i >> 9;          // i / 768... careful: 768 not pow2
        q = i / 768;
        int c = i - q * 768;
        ws[c * 16 + q] = wp[i];
    }
    __syncthreads();

    const float* f = F + (size_t)b * 768 * 1024 + col;

    unsigned long long acc2[8];   // q-pairs (0,1),(2,3),...,(14,15)
    #pragma unroll
    for (int j = 0; j < 8; ++j) acc2[j] = 0ull;

    const int c0 = part * 96;
    for (int c = c0; c < c0 + 96; c += 8) {
        float fv[8];
        #pragma unroll
        for (int u = 0; u < 8; ++u)
            fv[u] = __ldg(&f[(size_t)(c + u) * 1024]);
        #pragma unroll
        for (int u = 0; u < 8; ++u) {
            const unsigned long long fb = bcast2(fv[u]);
            const ulonglong2* wrow = (const ulonglong2*)&ws[(c + u) * 16];
            #pragma unroll
            for (int g = 0; g < 4; ++g) {
                ulonglong2 wpair = wrow[g];    // lds.128: q 4g..4g+3
                ffma2(acc2[g * 2 + 0], fb, wpair.x);
                ffma2(acc2[g * 2 + 1], fb, wpair.y);
            }
        }
    }

    #pragma unroll
    for (int j = 0; j < 8; ++j) {
        red[part][j * 2 + 0][lane] = lo32(acc2[j]);
        red[part][j * 2 + 1][lane] = hi32(acc2[j]);
    }
    __syncthreads();

    if (part == 0) {
        float* op = out + (size_t)b * 16 * 1024 + col;
        const float* qp = Q + (size_t)b * 16 * 1024 + col;
        float lsum = 0.0f;
        #pragma unroll
        for (int q = 0; q < 16; ++q) {
            float s = red[0][q][lane] + red[1][q][lane]
                    + red[2][q][lane] + red[3][q][lane]
                    + red[4][q][lane] + red[5][q][lane]
                    + red[6][q][lane] + red[7][q][lane];
            op[(size_t)q * 1024] = s;
            float d = s - qp[(size_t)q * 1024];
            lsum += d * d;
        }
        #pragma unroll
        for (int off = 16; off > 0; off >>= 1)
            lsum += __shfl_xor_sync(0xffffffffu, lsum, off);
        if (lane == 0)
            g_loss_part[b * 32 + blockIdx.x] = lsum;
    }
}

__global__ void loss_final(float* __restrict__ out)
{
    __shared__ float s[1024];
    const int t = threadIdx.x;
    s[t] = g_loss_part[t];
    __syncthreads();
    for (int o = 512; o > 0; o >>= 1) {
        if (t < o) s[t] += s[t + o];
        __syncthreads();
    }
    if (t == 0) out[524320] = s[0] / 524288.0f;
}

extern "C" void kernel_launch(void* const* d_in, const int* in_sizes, int n_in,
                              void* d_out, int out_size)
{
    const float* F = (const float*)d_in[0];
    const float* Q = (const float*)d_in[1];
    const float* W = (const float*)d_in[2];
    float* out = (float*)d_out;

    cudaFuncSetAttribute(dist_gemm_mma,
                         cudaFuncAttributeMaxDynamicSharedMemorySize, DSMEM);
    cudaFuncSetAttribute(sel_kernel,
                         cudaFuncAttributeMaxDynamicSharedMemorySize, SEL_SMEM);

    conv_kernel<<<CONV_F_BLOCKS + CONV_W_BLOCKS, 256>>>(F, W);
    dist_gemm_mma<<<dim3(8, 8, 32), 128, DSMEM>>>(Q);
    argmin_kernel<<<1, 1024>>>(out);
    sel_kernel<<<dim3(32, 32), 256, SEL_SMEM>>>(F, Q, W, out);
    loss_final<<<1, 1024>>>(out);
}

// round 13
// speedup vs baseline: 1.2982x; 1.0997x over previous
#include <cuda_runtime.h>
#include <cuda_fp16.h>
#include <cstdint>

// features: [32, 768, 32, 32] -> F[b, c, hw], hw = 1024
// query:    [32, 16, 32, 32]  -> Q[b, q, hw]
// W:        [64, 16, 768]     -> A[r, c], r = k*16+q  (1024 x 768)
//
// dist2[b,k] = sum_{q,hw} (A@F_b - Q)^2 ; codes = argmin_k ; sel = recompute.
// GEMM in pure fp16 mma.sync (dist2 err std ~0.14 << argmin gap ~150).
// sel + commit_loss recomputed EXACTLY in fp32, so output precision is fp32.

#define FN   (32 * 768 * 1024)
#define WN   (1024 * 768)

__device__ __half g_Fh[FN];
__device__ __half g_Wh[WN];
__device__ float g_dist2_part[32 * 512];   // [b][k(64)][hwtile(8)]
__device__ int   g_codes[32];
__device__ float g_loss_part[1024];

// ---------------- PTX helpers ----------------
__device__ __forceinline__ uint32_t smem_u32(const void* p) {
    uint32_t a;
    asm("{ .reg .u64 t; cvta.to.shared.u64 t, %1; cvt.u32.u64 %0, t; }" : "=r"(a) : "l"(p));
    return a;
}
__device__ __forceinline__ void cp16(uint32_t dst, const void* src) {
    asm volatile("cp.async.cg.shared.global [%0], [%1], 16;" :: "r"(dst), "l"(src));
}
#define CP_COMMIT() asm volatile("cp.async.commit_group;" ::: "memory")
#define CP_WAIT(n)  asm volatile("cp.async.wait_group %0;" :: "n"(n) : "memory")

__device__ __forceinline__ void ldsm_x4(uint32_t addr, uint32_t* r) {
    asm volatile("ldmatrix.sync.aligned.m8n8.x4.shared.b16 {%0,%1,%2,%3}, [%4];"
                 : "=r"(r[0]), "=r"(r[1]), "=r"(r[2]), "=r"(r[3]) : "r"(addr));
}
__device__ __forceinline__ void ldsm_x4_t(uint32_t addr, uint32_t* r) {
    asm volatile("ldmatrix.sync.aligned.m8n8.x4.trans.shared.b16 {%0,%1,%2,%3}, [%4];"
                 : "=r"(r[0]), "=r"(r[1]), "=r"(r[2]), "=r"(r[3]) : "r"(addr));
}
__device__ __forceinline__ void mma_f16(float* c, const uint32_t* a, const uint32_t* b) {
    asm volatile(
        "mma.sync.aligned.m16n8k16.row.col.f32.f16.f16.f32 "
        "{%0,%1,%2,%3},{%4,%5,%6,%7},{%8,%9},{%0,%1,%2,%3};"
        : "+f"(c[0]), "+f"(c[1]), "+f"(c[2]), "+f"(c[3])
        : "r"(a[0]), "r"(a[1]), "r"(a[2]), "r"(a[3]), "r"(b[0]), "r"(b[1]));
}

// ---------------- fp32 -> fp16 pre-conversion (F and W in one launch) ----------------
#define CONV_F_BLOCKS 2048
#define CONV_W_BLOCKS 192
__global__ void conv_kernel(const float* __restrict__ F, const float* __restrict__ W) {
    if (blockIdx.x < CONV_F_BLOCKS) {
        const float4* src = (const float4*)F;
        __half2* h2 = reinterpret_cast<__half2*>(g_Fh);
        const int n4 = FN / 4;
        for (int i = blockIdx.x * blockDim.x + threadIdx.x; i < n4;
             i += CONV_F_BLOCKS * blockDim.x) {
            float4 v = src[i];
            h2[i * 2 + 0] = __floats2half2_rn(v.x, v.y);
            h2[i * 2 + 1] = __floats2half2_rn(v.z, v.w);
        }
    } else {
        const float4* src = (const float4*)W;
        __half2* h2 = reinterpret_cast<__half2*>(g_Wh);
        const int n4 = WN / 4;
        for (int i = (blockIdx.x - CONV_F_BLOCKS) * blockDim.x + threadIdx.x; i < n4;
             i += CONV_W_BLOCKS * blockDim.x) {
            float4 v = src[i];
            h2[i * 2 + 0] = __floats2half2_rn(v.x, v.y);
            h2[i * 2 + 1] = __floats2half2_rn(v.z, v.w);
        }
    }
}

// ---------------- dist GEMM: fp16 mma.sync (R8 structure, proven) ----------------
#define ST_B    10240
#define STAGE   18944
#define NSTAGE  5
#define DSMEM   (NSTAGE * STAGE + 64)

__device__ __forceinline__ void load_stage(
    int t, int kb, uint32_t sbase, int rowBase, int colBase, size_t Foff)
{
    #pragma unroll
    for (int it = 0; it < 4; ++it) {
        int o = it * 128 + t;
        int row = o >> 2, seg = o & 3;
        const __half* s = g_Wh + (size_t)(rowBase + row) * 768 + kb + seg * 8;
        cp16(sbase + row * 80 + seg * 16, s);
    }
    #pragma unroll
    for (int it = 0; it < 4; ++it) {
        int o = it * 128 + t;
        int row = o >> 4, seg = o & 15;
        const __half* s = g_Fh + Foff + (size_t)(kb + row) * 1024 + colBase + seg * 8;
        cp16(sbase + ST_B + row * 272 + seg * 16, s);
    }
}

__global__ __launch_bounds__(128, 2)
void dist_gemm_mma(const float* __restrict__ Q)
{
    extern __shared__ char smem[];
    const uint32_t sb = smem_u32(smem);
    float* sred = (float*)(smem + NSTAGE * STAGE);   // [8 k][2 colgrp]

    const int t    = threadIdx.x;
    const int wid  = t >> 5;
    const int lane = t & 31;
    const int wr   = wid & 1;
    const int wc   = wid >> 1;
    const int b       = blockIdx.z;
    const int rowBase = blockIdx.y * 128;
    const int colBase = blockIdx.x * 128;
    const size_t Foff = (size_t)b * 768 * 1024;

    uint32_t a_addr[4];
    #pragma unroll
    for (int rt = 0; rt < 4; ++rt) {
        int row = wr * 64 + rt * 16 + (lane & 15);
        a_addr[rt] = sb + row * 80 + ((lane >> 4) * 16);
    }
    uint32_t b_addr[4];
    #pragma unroll
    for (int p = 0; p < 4; ++p) {
        int n = wc * 64 + p * 16 + (lane >> 4) * 8;
        b_addr[p] = sb + ST_B + (lane & 15) * 272 + n * 2;
    }

    float acc[4][8][4];
    #pragma unroll
    for (int i = 0; i < 4; ++i)
        #pragma unroll
        for (int j = 0; j < 8; ++j)
            #pragma unroll
            for (int v = 0; v < 4; ++v) acc[i][j][v] = 0.0f;

    load_stage(t, 0, sb, rowBase, colBase, Foff);
    CP_COMMIT();
    load_stage(t, 32, sb + STAGE, rowBase, colBase, Foff);
    CP_COMMIT();
    load_stage(t, 64, sb + 2 * STAGE, rowBase, colBase, Foff);
    CP_COMMIT();

    for (int kt = 0; kt < 24; ++kt) {
        if (kt + 3 < 24)
            load_stage(t, (kt + 3) * 32, sb + ((kt + 3) % NSTAGE) * STAGE,
                       rowBase, colBase, Foff);
        CP_COMMIT();
        CP_WAIT(3);           // this warp's chunk-kt copies resident
        __syncthreads();      // -> ALL warps' chunk-kt copies visible

        const uint32_t soff = (kt % NSTAGE) * STAGE;
        #pragma unroll
        for (int ks = 0; ks < 2; ++ks) {
            uint32_t ah[4][4], bh[16];
            const uint32_t aoff = soff + ks * 32;
            const uint32_t boff = soff + ks * (16 * 272);
            #pragma unroll
            for (int rt = 0; rt < 4; ++rt)
                ldsm_x4(a_addr[rt] + aoff, ah[rt]);
            #pragma unroll
            for (int p = 0; p < 4; ++p)
                ldsm_x4_t(b_addr[p] + boff, &bh[p * 4]);
            #pragma unroll
            for (int rt = 0; rt < 4; ++rt)
                #pragma unroll
                for (int nt = 0; nt < 8; ++nt)
                    mma_f16(acc[rt][nt], ah[rt], &bh[nt * 2]);
        }
    }

    // ---- epilogue: (C - Q)^2, deterministic reduction per k-group ----
    const int qr0 = lane >> 2;
    const int cb  = colBase + wc * 64;
    float2 qa[8], qb[8];
    #pragma unroll
    for (int nt = 0; nt < 8; ++nt) {
        const float* q0 = Q + (size_t)b * 16384 + (size_t)qr0 * 1024 + cb + nt * 8 + (lane & 3) * 2;
        qa[nt] = *(const float2*)q0;
        qb[nt] = *(const float2*)(q0 + 8 * 1024);
    }
    __syncthreads();
    #pragma unroll
    for (int rt = 0; rt < 4; ++rt) {
        float rs = 0.0f;
        #pragma unroll
        for (int nt = 0; nt < 8; ++nt) {
            float d0 = acc[rt][nt][0] - qa[nt].x;
            float d1 = acc[rt][nt][1] - qa[nt].y;
            float d2 = acc[rt][nt][2] - qb[nt].x;
            float d3 = acc[rt][nt][3] - qb[nt].y;
            rs += d0 * d0 + d1 * d1 + d2 * d2 + d3 * d3;
        }
        #pragma unroll
        for (int off = 16; off > 0; off >>= 1)
            rs += __shfl_xor_sync(0xffffffffu, rs, off);
        if (lane == 0) sred[(wr * 4 + rt) * 2 + wc] = rs;
    }
    __syncthreads();
    if (t < 8) {
        float s = sred[t * 2 + 0] + sred[t * 2 + 1];
        const int k = blockIdx.y * 8 + t;
        g_dist2_part[b * 512 + k * 8 + blockIdx.x] = s;
    }
}

// ---------------- argmin: 1 block, warp-per-batch ----------------
__global__ __launch_bounds__(1024)
void argmin_kernel(float* __restrict__ out)
{
    const int b    = threadIdx.x >> 5;
    const int lane = threadIdx.x & 31;

    float v[2];
    #pragma unroll
    for (int j = 0; j < 2; ++j) {
        const int k = lane * 2 + j;
        const float4* p = (const float4*)(g_dist2_part + b * 512 + k * 8);
        float4 x = p[0], y = p[1];
        v[j] = (x.x + x.y) + (x.z + x.w) + (y.x + y.y) + (y.z + y.w);
    }
    float best = v[0] < v[1] ? v[0] : v[1];
    int   bi   = v[0] < v[1] ? lane * 2 : lane * 2 + 1;
    #pragma unroll
    for (int off = 16; off > 0; off >>= 1) {
        float ov = __shfl_xor_sync(0xffffffffu, best, off);
        int   oi = __shfl_xor_sync(0xffffffffu, bi,   off);
        if (ov < best || (ov == best && oi < bi)) { best = ov; bi = oi; }
    }
    if (lane == 0) {
        g_codes[b] = bi;
        out[524288 + b] = (float)bi;
    }
}

// ---------------- sel recompute (fp32 exact) + loss partials ----------------
// grid = (32 col-tiles, 32 batches), 256 threads = 32 cols x 8 c-partitions.
// 16-deep F load batches for DRAM MLP; W via warp-uniform L1-resident __ldg.
__global__ __launch_bounds__(256, 4)
void sel_kernel(const float* __restrict__ F,
                const float* __restrict__ Q,
                const float* __restrict__ W,
                float* __restrict__ out)
{
    __shared__ float red[8][16][32];   // 16 KB
    const int b    = blockIdx.y;
    const int lane = threadIdx.x & 31;
    const int part = threadIdx.x >> 5;       // 0..7, each owns 96 c's
    const int col  = blockIdx.x * 32 + lane;
    const int code = g_codes[b];

    const float* wp = W + (size_t)code * 16 * 768;
    const float* f  = F + (size_t)b * 768 * 1024 + col;

    float acc[16];
    #pragma unroll
    for (int q = 0; q < 16; ++q) acc[q] = 0.0f;

    const int c0 = part * 96;
    for (int it = 0; it < 6; ++it) {
        const int c = c0 + it * 16;
        float fv[16];
        #pragma unroll
        for (int u = 0; u < 16; ++u)
            fv[u] = __ldg(&f[(size_t)(c + u) * 1024]);
        #pragma unroll
        for (int q = 0; q < 16; ++q) {
            const float4 w0 = *(const float4*)&wp[q * 768 + c];
            const float4 w1 = *(const float4*)&wp[q * 768 + c + 4];
            const float4 w2 = *(const float4*)&wp[q * 768 + c + 8];
            const float4 w3 = *(const float4*)&wp[q * 768 + c + 12];
            acc[q] += w0.x * fv[0]  + w0.y * fv[1]  + w0.z * fv[2]  + w0.w * fv[3];
            acc[q] += w1.x * fv[4]  + w1.y * fv[5]  + w1.z * fv[6]  + w1.w * fv[7];
            acc[q] += w2.x * fv[8]  + w2.y * fv[9]  + w2.z * fv[10] + w2.w * fv[11];
            acc[q] += w3.x * fv[12] + w3.y * fv[13] + w3.z * fv[14] + w3.w * fv[15];
        }
    }

    #pragma unroll
    for (int q = 0; q < 16; ++q) red[part][q][lane] = acc[q];
    __syncthreads();

    if (part == 0) {
        float* op = out + (size_t)b * 16 * 1024 + col;
        const float* qp = Q + (size_t)b * 16 * 1024 + col;
        float lsum = 0.0f;
        #pragma unroll
        for (int q = 0; q < 16; ++q) {
            float s = red[0][q][lane] + red[1][q][lane]
                    + red[2][q][lane] + red[3][q][lane]
                    + red[4][q][lane] + red[5][q][lane]
                    + red[6][q][lane] + red[7][q][lane];
            op[(size_t)q * 1024] = s;
            float d = s - qp[(size_t)q * 1024];
            lsum += d * d;
        }
        #pragma unroll
        for (int off = 16; off > 0; off >>= 1)
            lsum += __shfl_xor_sync(0xffffffffu, lsum, off);
        if (lane == 0)
            g_loss_part[b * 32 + blockIdx.x] = lsum;
    }
}

__global__ void loss_final(float* __restrict__ out)
{
    __shared__ float s[1024];
    const int t = threadIdx.x;
    s[t] = g_loss_part[t];
    __syncthreads();
    for (int o = 512; o > 0; o >>= 1) {
        if (t < o) s[t] += s[t + o];
        __syncthreads();
    }
    if (t == 0) out[524320] = s[0] / 524288.0f;
}

extern "C" void kernel_launch(void* const* d_in, const int* in_sizes, int n_in,
                              void* d_out, int out_size)
{
    const float* F = (const float*)d_in[0];
    const float* Q = (const float*)d_in[1];
    const float* W = (const float*)d_in[2];
    float* out = (float*)d_out;

    cudaFuncSetAttribute(dist_gemm_mma,
                         cudaFuncAttributeMaxDynamicSharedMemorySize, DSMEM);

    conv_kernel<<<CONV_F_BLOCKS + CONV_W_BLOCKS, 256>>>(F, W);
    dist_gemm_mma<<<dim3(8, 8, 32), 128, DSMEM>>>(Q);
    argmin_kernel<<<1, 1024>>>(out);
    sel_kernel<<<dim3(32, 32), 256>>>(F, Q, W, out);
    loss_final<<<1, 1024>>>(out);
}